// round 9
// baseline (speedup 1.0000x reference)
#include <cuda_runtime.h>
#include <cuda_fp16.h>
#include <cstdint>

// ============================================================================
// Problem constants
// ============================================================================
#define TOK   16384      // 4 * 4096 tokens
#define F     2048       // in/out features

// ============================================================================
// Device scratch (static globals — allocation-free per harness rules)
// ============================================================================
__device__ __half    g_W[F * F];       // W_eff fp16 (8.4 MB)
__device__ __half    g_X[TOK * F];     // x fp16 (67 MB)
__device__ unsigned  g_cnt[TOK / 128]; // per-panel conversion counters (128)

// ============================================================================
// Helpers
// ============================================================================
__device__ __forceinline__ uint32_t smem_to_u32(const void* p) {
    uint32_t a;
    asm("{ .reg .u64 t; cvta.to.shared.u64 t, %1; cvt.u32.u64 %0, t; }"
        : "=r"(a) : "l"(p));
    return a;
}

__device__ __forceinline__ unsigned ld_acquire_gpu(const unsigned* p) {
    unsigned v;
    asm volatile("ld.acquire.gpu.global.b32 %0, [%1];" : "=r"(v) : "l"(p));
    return v;
}

// ============================================================================
// Fold kernel: W_eff = stage2 ∘ shuffle ∘ mix ∘ stage1 collapsed to one matrix.
// Also zeroes the per-panel counters for the GEMM (fresh each graph replay).
// Block b -> (ot = b>>5, g = b&31):
//   M[ot*64+oo, g*64+dd] = sum_c stage2[ot*64+c, oo] * mix_w[ot*64+c, sig(g*64+dd)]
//   W[ot*64+oo, g*64+c2] = sum_dd M[oo][dd] * stage1[g*64+c2, dd]
//   sig(m) = (m%32)*64 + m/32
// ============================================================================
__global__ __launch_bounds__(256)
void fold_kernel(const float* __restrict__ stage1,
                 const float* __restrict__ stage2,
                 const float* __restrict__ mix_w) {
    __shared__ float bufA[64 * 65];
    __shared__ float bufB[64 * 65];

    const int b = blockIdx.x;
    const int tid = threadIdx.x;
    const int ot = b >> 5, g = b & 31;

    if (b == 0 && tid < TOK / 128) g_cnt[tid] = 0;   // reset panel counters

    for (int i = tid; i < 64 * 64; i += 256) {
        int c = i >> 6, d = i & 63;
        bufA[c * 64 + d] = stage2[(ot * 64 + c) * 64 + d];
    }
    for (int i = tid; i < 64 * 64; i += 256) {
        int c = i >> 6, dd = i & 63;
        int m = g * 64 + dd;
        int sig = (m & 31) * 64 + (m >> 5);
        bufB[c * 64 + dd] = mix_w[(size_t)(ot * 64 + c) * F + sig];
    }
    __syncthreads();

    const int j = tid & 63, q = tid >> 6;
    float macc[16];
#pragma unroll
    for (int k = 0; k < 16; k++) macc[k] = 0.0f;
    for (int c = 0; c < 64; c++) {
        float mx = bufB[c * 64 + j];
#pragma unroll
        for (int k = 0; k < 16; k++) macc[k] += bufA[c * 64 + q * 16 + k] * mx;
    }
    __syncthreads();

#pragma unroll
    for (int k = 0; k < 16; k++) bufA[(q * 16 + k) * 65 + j] = macc[k];
    for (int i = tid; i < 64 * 64; i += 256) {
        int c2 = i >> 6, dd = i & 63;
        bufB[c2 * 65 + dd] = stage1[(g * 64 + c2) * 64 + dd];
    }
    __syncthreads();

    const int c2 = tid & 63;
    float wacc[16];
#pragma unroll
    for (int k = 0; k < 16; k++) wacc[k] = 0.0f;
    for (int dd = 0; dd < 64; dd++) {
        float w1 = bufB[c2 * 65 + dd];
#pragma unroll
        for (int k = 0; k < 16; k++) wacc[k] += bufA[(q * 16 + k) * 65 + dd] * w1;
    }
#pragma unroll
    for (int k = 0; k < 16; k++)
        g_W[(size_t)(ot * 64 + q * 16 + k) * F + g * 64 + c2] = __float2half_rn(wacc[k]);
}

// ============================================================================
// Main GEMM: out[t, o] = sum_k x[t,k] * W[o,k]   (fp16 inputs, fp32 accum)
//   - distributed in-kernel x->fp16 conversion + panel barrier (R7)
//   - ks-level fragment double-buffering: LDSM for ks+1 overlaps MMAs of ks
//   - MMA asm non-volatile so ptxas can fill LDSM shadows
// CTA tile 128x128, K chunk 64, 3-stage cp.async, 8 warps (2x4 of 64x32).
// ============================================================================
static constexpr int BM = 128, BN = 128, BK = 64, STAGES = 3;
static constexpr int A_STAGE_BYTES = BM * BK * 2;               // 16384
static constexpr int STAGE_BYTES   = (BM + BN) * BK * 2;        // 32768
static constexpr int SMEM_BYTES    = STAGES * STAGE_BYTES;      // 98304

__global__ __launch_bounds__(256, 2)
void gemm_kernel(const float* __restrict__ x, float* __restrict__ out) {
    extern __shared__ char smem[];
    const uint32_t sbase = smem_to_u32(smem);
    const int tid  = threadIdx.x;
    const int lane = tid & 31, wid = tid >> 5;
    const int m0 = blockIdx.y * BM;
    const int n0 = blockIdx.x * BN;
    const int wm = (wid >> 2) * 64;     // warp m-origin in tile
    const int wn = (wid & 3) * 32;      // warp n-origin in tile

    // ---- distributed conversion: blockIdx.x owns 8 rows of panel m0 ----
    {
        const size_t base = ((size_t)m0 + (size_t)blockIdx.x * 8) * F;
#pragma unroll 8
        for (int it = 0; it < 16; it++) {
            size_t off = base + (size_t)it * 1024 + (size_t)tid * 4;
            float4 v = *(const float4*)(x + off);
            __half2 h0 = __floats2half2_rn(v.x, v.y);
            __half2 h1 = __floats2half2_rn(v.z, v.w);
            uint2 w;
            w.x = *(uint32_t*)&h0; w.y = *(uint32_t*)&h1;
            *(uint2*)(g_X + off) = w;
        }
        __threadfence();
        __syncthreads();
        if (tid == 0) {
            atomicAdd(&g_cnt[blockIdx.y], 1u);
            while (ld_acquire_gpu(&g_cnt[blockIdx.y]) < 16u) { }
        }
        __syncthreads();
    }

    // ---- cp.async geometry: base + constant stride (row+32 keeps swizzle) ----
    const int row0 = tid >> 3, seg = tid & 7;
    const uint32_t dst0 = (uint32_t)(row0 * 128 + ((seg ^ (row0 & 7)) * 16));
    const __half* pa0 = g_X + (size_t)(m0 + row0) * F + seg * 8;
    const __half* pb0 = g_W + (size_t)(n0 + row0) * F + seg * 8;

    auto issue_stage = [&](int kc, int st) {
        uint32_t sA = sbase + st * STAGE_BYTES + dst0;
        uint32_t sB = sA + A_STAGE_BYTES;
        const __half* pa = pa0 + (size_t)kc * BK;
        const __half* pb = pb0 + (size_t)kc * BK;
#pragma unroll
        for (int i = 0; i < 4; i++) {
            asm volatile("cp.async.cg.shared.global [%0], [%1], 16;"
                         :: "r"(sA + i * 32 * 128), "l"(pa + i * 32 * F) : "memory");
            asm volatile("cp.async.cg.shared.global [%0], [%1], 16;"
                         :: "r"(sB + i * 32 * 128), "l"(pb + i * 32 * F) : "memory");
        }
    };

    // ---- ldmatrix per-lane addressing ----
    const uint32_t aBase = (uint32_t)(wm + (lane & 15)) * 128u;
    const uint32_t bBase = (uint32_t)(wn + ((lane & 7) | ((lane & 16) >> 1))) * 128u;
    const uint32_t aSel = (uint32_t)(lane >> 4);         // 0/1
    const uint32_t bSel = (uint32_t)((lane >> 3) & 1);   // 0/1
    const uint32_t swz  = (uint32_t)(lane & 7);

    float acc[4][4][4];
#pragma unroll
    for (int fm = 0; fm < 4; fm++)
#pragma unroll
        for (int fn = 0; fn < 4; fn++)
#pragma unroll
            for (int k = 0; k < 4; k++) acc[fm][fn][k] = 0.0f;

    uint32_t af[2][4][4], bf[2][8];   // double-buffered fragments

    auto ldfrags = [&](uint32_t sA, uint32_t sB, int ks, int buf) {
        uint32_t xa = (((uint32_t)(ks * 2) + aSel) ^ swz) * 16u;
        uint32_t xb = (((uint32_t)(ks * 2) + bSel) ^ swz) * 16u;
#pragma unroll
        for (int fm = 0; fm < 4; fm++) {
            uint32_t addr = sA + (uint32_t)(fm * 2048) + xa;
            asm volatile(
                "ldmatrix.sync.aligned.m8n8.x4.shared.b16 {%0,%1,%2,%3}, [%4];"
                : "=r"(af[buf][fm][0]), "=r"(af[buf][fm][1]),
                  "=r"(af[buf][fm][2]), "=r"(af[buf][fm][3])
                : "r"(addr));
        }
#pragma unroll
        for (int p = 0; p < 2; p++) {
            uint32_t addr = sB + (uint32_t)(p * 2048) + xb;
            asm volatile(
                "ldmatrix.sync.aligned.m8n8.x4.shared.b16 {%0,%1,%2,%3}, [%4];"
                : "=r"(bf[buf][p*4+0]), "=r"(bf[buf][p*4+1]),
                  "=r"(bf[buf][p*4+2]), "=r"(bf[buf][p*4+3])
                : "r"(addr));
        }
    };

    auto mmas = [&](int buf) {
#pragma unroll
        for (int fm = 0; fm < 4; fm++) {
#pragma unroll
            for (int fn = 0; fn < 4; fn++) {
                uint32_t b0 = bf[buf][(fn >> 1) * 4 + (fn & 1) * 2];
                uint32_t b1 = bf[buf][(fn >> 1) * 4 + (fn & 1) * 2 + 1];
                // non-volatile: let ptxas interleave into LDSM shadows
                asm("mma.sync.aligned.m16n8k16.row.col.f32.f16.f16.f32 "
                    "{%0,%1,%2,%3}, {%4,%5,%6,%7}, {%8,%9}, {%0,%1,%2,%3};"
                    : "+f"(acc[fm][fn][0]), "+f"(acc[fm][fn][1]),
                      "+f"(acc[fm][fn][2]), "+f"(acc[fm][fn][3])
                    : "r"(af[buf][fm][0]), "r"(af[buf][fm][1]),
                      "r"(af[buf][fm][2]), "r"(af[buf][fm][3]),
                      "r"(b0), "r"(b1));
            }
        }
    };

    // ---- pipeline ----
    issue_stage(0, 0);
    asm volatile("cp.async.commit_group;" ::: "memory");
    issue_stage(1, 1);
    asm volatile("cp.async.commit_group;" ::: "memory");

    const int NCHUNK = F / BK;   // 32
    for (int kc = 0; kc < NCHUNK; kc++) {
        asm volatile("cp.async.wait_group 1;" ::: "memory");
        __syncthreads();
        if (kc + 2 < NCHUNK) {
            int nxt = kc + 2;
            issue_stage(nxt, nxt % STAGES);
        }
        asm volatile("cp.async.commit_group;" ::: "memory");

        const int st = kc % STAGES;
        const uint32_t sA = sbase + st * STAGE_BYTES + aBase;
        const uint32_t sB = sbase + st * STAGE_BYTES + A_STAGE_BYTES + bBase;
        // ks-pipelined: prefetch ks+1 frags before MMAs of ks
        ldfrags(sA, sB, 0, 0);
#pragma unroll
        for (int ks = 0; ks < 4; ks++) {
            const int cur = ks & 1;
            if (ks < 3) ldfrags(sA, sB, ks + 1, cur ^ 1);
            mmas(cur);
        }
    }

    // ---- epilogue: direct fp32 stores ----
#pragma unroll
    for (int fm = 0; fm < 4; fm++) {
#pragma unroll
        for (int fn = 0; fn < 4; fn++) {
            int r = m0 + wm + fm * 16 + (lane >> 2);
            int c = n0 + wn + fn * 8 + (lane & 3) * 2;
            float2 v0 = make_float2(acc[fm][fn][0], acc[fm][fn][1]);
            float2 v1 = make_float2(acc[fm][fn][2], acc[fm][fn][3]);
            *(float2*)(out + (size_t)r * F + c)       = v0;
            *(float2*)(out + (size_t)(r + 8) * F + c) = v1;
        }
    }
}

// ============================================================================
// Launch
// ============================================================================
extern "C" void kernel_launch(void* const* d_in, const int* in_sizes, int n_in,
                              void* d_out, int out_size) {
    const float* x      = (const float*)d_in[0];
    const float* stage1 = (const float*)d_in[1];
    const float* stage2 = (const float*)d_in[2];
    const float* mix_w  = (const float*)d_in[3];
    float* out = (float*)d_out;

    cudaFuncSetAttribute(gemm_kernel,
                         cudaFuncAttributeMaxDynamicSharedMemorySize, SMEM_BYTES);

    fold_kernel<<<1024, 256>>>(stage1, stage2, mix_w);
    gemm_kernel<<<dim3(F / BN, TOK / BM), 256, SMEM_BYTES>>>(x, out);
}

// round 10
// speedup vs baseline: 1.0357x; 1.0357x over previous
#include <cuda_runtime.h>
#include <cuda_fp16.h>
#include <cstdint>

// ============================================================================
// Problem constants
// ============================================================================
#define TOK   16384      // 4 * 4096 tokens
#define F     2048       // in/out features

// ============================================================================
// Device scratch (static globals — allocation-free per harness rules)
// ============================================================================
__device__ __half    g_W[F * F];        // W_eff fp16 (8.4 MB)
__device__ __half    g_X[TOK * F];      // x fp16 (67 MB)
__device__ unsigned  g_cnt[TOK / 128];  // per-token-panel conversion counters (128)
__device__ unsigned  g_fcnt[F / 128];   // per-W-panel fold counters (16)

// ============================================================================
// Helpers
// ============================================================================
__device__ __forceinline__ uint32_t smem_to_u32(const void* p) {
    uint32_t a;
    asm("{ .reg .u64 t; cvta.to.shared.u64 t, %1; cvt.u32.u64 %0, t; }"
        : "=r"(a) : "l"(p));
    return a;
}

__device__ __forceinline__ unsigned ld_acquire_gpu(const unsigned* p) {
    unsigned v;
    asm volatile("ld.acquire.gpu.global.b32 %0, [%1];" : "=r"(v) : "l"(p));
    return v;
}

// ============================================================================
// Init kernel: zero the rendezvous counters (fresh each graph replay).
// ============================================================================
__global__ void init_kernel() {
    int t = threadIdx.x;
    if (t < F / 128) g_fcnt[t] = 0;
    if (t < TOK / 128) g_cnt[t] = 0;
}

// ============================================================================
// Main kernel. Phases per CTA (bx, by):
//  1. (by < 16 only) fold 4 weight blocks (ot in {2bx,2bx+1}, g in {2by,2by+1})
//     -> produces exactly the W rows this bx column needs; signal g_fcnt[bx].
//  2. convert 8 rows of x panel by -> fp16; signal g_cnt[by].
//  3. rendezvous: wait g_cnt[by]==16 and g_fcnt[bx]==16.
//  4. R7 mainloop: 128x128 tile, 3-stage cp.async, 8 warps (2x4 of 64x32).
// ============================================================================
static constexpr int BM = 128, BN = 128, BK = 64, STAGES = 3;
static constexpr int A_STAGE_BYTES = BM * BK * 2;               // 16384
static constexpr int STAGE_BYTES   = (BM + BN) * BK * 2;        // 32768
static constexpr int SMEM_BYTES    = STAGES * STAGE_BYTES;      // 98304

__global__ __launch_bounds__(256, 2)
void gemm_kernel(const float* __restrict__ x,
                 const float* __restrict__ stage1,
                 const float* __restrict__ stage2,
                 const float* __restrict__ mix_w,
                 float* __restrict__ out) {
    extern __shared__ char smem[];
    const uint32_t sbase = smem_to_u32(smem);
    const int tid  = threadIdx.x;
    const int lane = tid & 31, wid = tid >> 5;
    const int bx = blockIdx.x, by = blockIdx.y;
    const int m0 = by * BM;
    const int n0 = bx * BN;
    const int wm = (wid >> 2) * 64;
    const int wn = (wid & 3) * 32;

    // ======== Phase 1: distributed weight fold (CTAs with by < 16) ========
    if (by < 16) {
        float* bufA = (float*)smem;              // 64x65
        float* bufB = bufA + 64 * 65;            // 64x65  (33.3 KB total)
        const int j = tid & 63, q = tid >> 6;

        for (int sub = 0; sub < 4; sub++) {
            const int ot = 2 * bx + (sub >> 1);
            const int g  = 2 * by + (sub & 1);

            // Phase A: stage2 block [c][d] and permuted mix_w block [c][dd]
            for (int i = tid; i < 64 * 64; i += 256) {
                int c = i >> 6, d = i & 63;
                bufA[c * 64 + d] = stage2[(ot * 64 + c) * 64 + d];
            }
            for (int i = tid; i < 64 * 64; i += 256) {
                int c = i >> 6, dd = i & 63;
                int m = g * 64 + dd;
                int sig = (m & 31) * 64 + (m >> 5);
                bufB[c * 64 + dd] = mix_w[(size_t)(ot * 64 + c) * F + sig];
            }
            __syncthreads();

            // Phase B: M-block partial in registers
            float macc[16];
#pragma unroll
            for (int k = 0; k < 16; k++) macc[k] = 0.0f;
            for (int c = 0; c < 64; c++) {
                float mx = bufB[c * 64 + j];
#pragma unroll
                for (int k = 0; k < 16; k++) macc[k] += bufA[c * 64 + q * 16 + k] * mx;
            }
            __syncthreads();

            // Phase C: materialize M (stride 65) into bufA; load stage1
#pragma unroll
            for (int k = 0; k < 16; k++) bufA[(q * 16 + k) * 65 + j] = macc[k];
            for (int i = tid; i < 64 * 64; i += 256) {
                int c2 = i >> 6, dd = i & 63;
                bufB[c2 * 65 + dd] = stage1[(g * 64 + c2) * 64 + dd];
            }
            __syncthreads();

            // Phase D: contract with stage1, emit fp16
            float wacc[16];
#pragma unroll
            for (int k = 0; k < 16; k++) wacc[k] = 0.0f;
            for (int dd = 0; dd < 64; dd++) {
                float w1 = bufB[j * 65 + dd];
#pragma unroll
                for (int k = 0; k < 16; k++) wacc[k] += bufA[(q * 16 + k) * 65 + dd] * w1;
            }
#pragma unroll
            for (int k = 0; k < 16; k++)
                g_W[(size_t)(ot * 64 + q * 16 + k) * F + g * 64 + j] =
                    __float2half_rn(wacc[k]);
            __syncthreads();   // buffers reused next sub
        }
        __threadfence();
        __syncthreads();
        if (tid == 0) atomicAdd(&g_fcnt[bx], 1u);
    }

    // ======== Phase 2: distributed x conversion (8 rows of panel by) ========
    {
        const size_t base = ((size_t)m0 + (size_t)bx * 8) * F;
#pragma unroll 8
        for (int it = 0; it < 16; it++) {
            size_t off = base + (size_t)it * 1024 + (size_t)tid * 4;
            float4 v = *(const float4*)(x + off);
            __half2 h0 = __floats2half2_rn(v.x, v.y);
            __half2 h1 = __floats2half2_rn(v.z, v.w);
            uint2 w;
            w.x = *(uint32_t*)&h0; w.y = *(uint32_t*)&h1;
            *(uint2*)(g_X + off) = w;
        }
        __threadfence();
        __syncthreads();
        if (tid == 0) {
            atomicAdd(&g_cnt[by], 1u);
            while (ld_acquire_gpu(&g_cnt[by]) < 16u) { }
            while (ld_acquire_gpu(&g_fcnt[bx]) < 16u) { }
        }
        __syncthreads();
    }

    // ======== Phase 3: R7 mainloop (verbatim) ========
    uint32_t dst_off[4];
    size_t   srcA[4], srcB[4];
#pragma unroll
    for (int i = 0; i < 4; i++) {
        int u = tid + 256 * i;                // 0..1023
        int row = u >> 3, seg = u & 7;        // 128 rows x 8 segs of 16B
        dst_off[i] = (uint32_t)(row * 128 + ((seg ^ (row & 7)) * 16));
        srcA[i] = (size_t)(m0 + row) * F + seg * 8;
        srcB[i] = (size_t)(n0 + row) * F + seg * 8;
    }
    const __half* gA = g_X;
    const __half* gB = g_W;

    auto issue_stage = [&](int kc, int st) {
        uint32_t sA = sbase + st * STAGE_BYTES;
        uint32_t sB = sA + A_STAGE_BYTES;
        const __half* pa = gA + (size_t)kc * BK;
        const __half* pb = gB + (size_t)kc * BK;
#pragma unroll
        for (int i = 0; i < 4; i++) {
            asm volatile("cp.async.cg.shared.global [%0], [%1], 16;"
                         :: "r"(sA + dst_off[i]), "l"(pa + srcA[i]) : "memory");
            asm volatile("cp.async.cg.shared.global [%0], [%1], 16;"
                         :: "r"(sB + dst_off[i]), "l"(pb + srcB[i]) : "memory");
        }
    };

    const uint32_t aRow = (uint32_t)(wm + (lane & 15));
    const uint32_t bRow = (uint32_t)(wn + ((lane & 7) | ((lane & 16) >> 1)));
    uint32_t xsA[4], xsB[4];
#pragma unroll
    for (int ks = 0; ks < 4; ks++) {
        xsA[ks] = (uint32_t)(((ks * 2 + (lane >> 4)) ^ (lane & 7)) * 16);
        xsB[ks] = (uint32_t)(((ks * 2 + ((lane >> 3) & 1)) ^ (lane & 7)) * 16);
    }
    const uint32_t aBase = aRow * 128u;
    const uint32_t bBase = bRow * 128u;

    float acc[4][4][4];
#pragma unroll
    for (int fm = 0; fm < 4; fm++)
#pragma unroll
        for (int fn = 0; fn < 4; fn++)
#pragma unroll
            for (int k = 0; k < 4; k++) acc[fm][fn][k] = 0.0f;

    auto compute_stage = [&](int st) {
        uint32_t sA = sbase + st * STAGE_BYTES + aBase;
        uint32_t sB = sbase + st * STAGE_BYTES + A_STAGE_BYTES + bBase;
#pragma unroll
        for (int ks = 0; ks < 4; ks++) {
            uint32_t a[4][4], b[8];
#pragma unroll
            for (int fm = 0; fm < 4; fm++) {
                uint32_t addr = sA + (uint32_t)(fm * 2048) + xsA[ks];
                asm volatile(
                    "ldmatrix.sync.aligned.m8n8.x4.shared.b16 {%0,%1,%2,%3}, [%4];"
                    : "=r"(a[fm][0]), "=r"(a[fm][1]), "=r"(a[fm][2]), "=r"(a[fm][3])
                    : "r"(addr));
            }
#pragma unroll
            for (int p = 0; p < 2; p++) {
                uint32_t addr = sB + (uint32_t)(p * 2048) + xsB[ks];
                asm volatile(
                    "ldmatrix.sync.aligned.m8n8.x4.shared.b16 {%0,%1,%2,%3}, [%4];"
                    : "=r"(b[p*4+0]), "=r"(b[p*4+1]), "=r"(b[p*4+2]), "=r"(b[p*4+3])
                    : "r"(addr));
            }
#pragma unroll
            for (int fm = 0; fm < 4; fm++) {
#pragma unroll
                for (int fn = 0; fn < 4; fn++) {
                    uint32_t b0 = b[(fn >> 1) * 4 + (fn & 1) * 2];
                    uint32_t b1 = b[(fn >> 1) * 4 + (fn & 1) * 2 + 1];
                    asm volatile(
                        "mma.sync.aligned.m16n8k16.row.col.f32.f16.f16.f32 "
                        "{%0,%1,%2,%3}, {%4,%5,%6,%7}, {%8,%9}, {%0,%1,%2,%3};"
                        : "+f"(acc[fm][fn][0]), "+f"(acc[fm][fn][1]),
                          "+f"(acc[fm][fn][2]), "+f"(acc[fm][fn][3])
                        : "r"(a[fm][0]), "r"(a[fm][1]), "r"(a[fm][2]), "r"(a[fm][3]),
                          "r"(b0), "r"(b1));
                }
            }
        }
    };

    issue_stage(0, 0);
    asm volatile("cp.async.commit_group;" ::: "memory");
    issue_stage(1, 1);
    asm volatile("cp.async.commit_group;" ::: "memory");

    const int NCHUNK = F / BK;   // 32
    for (int kc = 0; kc < NCHUNK; kc++) {
        asm volatile("cp.async.wait_group 1;" ::: "memory");
        __syncthreads();
        if (kc + 2 < NCHUNK) {
            int nxt = kc + 2;
            issue_stage(nxt, nxt % STAGES);
        }
        asm volatile("cp.async.commit_group;" ::: "memory");
        compute_stage(kc % STAGES);
    }

    // ---- epilogue: direct fp32 stores ----
#pragma unroll
    for (int fm = 0; fm < 4; fm++) {
#pragma unroll
        for (int fn = 0; fn < 4; fn++) {
            int r = m0 + wm + fm * 16 + (lane >> 2);
            int c = n0 + wn + fn * 8 + (lane & 3) * 2;
            float2 v0 = make_float2(acc[fm][fn][0], acc[fm][fn][1]);
            float2 v1 = make_float2(acc[fm][fn][2], acc[fm][fn][3]);
            *(float2*)(out + (size_t)r * F + c)       = v0;
            *(float2*)(out + (size_t)(r + 8) * F + c) = v1;
        }
    }
}

// ============================================================================
// Launch
// ============================================================================
extern "C" void kernel_launch(void* const* d_in, const int* in_sizes, int n_in,
                              void* d_out, int out_size) {
    const float* x      = (const float*)d_in[0];
    const float* stage1 = (const float*)d_in[1];
    const float* stage2 = (const float*)d_in[2];
    const float* mix_w  = (const float*)d_in[3];
    float* out = (float*)d_out;

    cudaFuncSetAttribute(gemm_kernel,
                         cudaFuncAttributeMaxDynamicSharedMemorySize, SMEM_BYTES);

    init_kernel<<<1, 256>>>();
    gemm_kernel<<<dim3(F / BN, TOK / BM), 256, SMEM_BYTES>>>(
        x, stage1, stage2, mix_w, out);
}

// round 11
// speedup vs baseline: 1.0652x; 1.0285x over previous
#include <cuda_runtime.h>
#include <cuda_fp16.h>
#include <cstdint>

// ============================================================================
// Problem constants
// ============================================================================
#define TOK   16384      // 4 * 4096 tokens
#define F     2048       // in/out features

// ============================================================================
// Device scratch (static globals — allocation-free per harness rules)
// ============================================================================
__device__ __half    g_W[F * F];       // W_eff fp16 (8.4 MB)
__device__ __half    g_X[TOK * F];     // x fp16 (67 MB)
__device__ unsigned  g_cnt[TOK / 128]; // per-panel conversion counters (128)

// ============================================================================
// Helpers
// ============================================================================
__device__ __forceinline__ uint32_t smem_to_u32(const void* p) {
    uint32_t a;
    asm("{ .reg .u64 t; cvta.to.shared.u64 t, %1; cvt.u32.u64 %0, t; }"
        : "=r"(a) : "l"(p));
    return a;
}

__device__ __forceinline__ unsigned ld_acquire_gpu(const unsigned* p) {
    unsigned v;
    asm volatile("ld.acquire.gpu.global.b32 %0, [%1];" : "=r"(v) : "l"(p));
    return v;
}

// ============================================================================
// Fold kernel: W_eff = stage2 ∘ shuffle ∘ mix ∘ stage1 collapsed to one matrix.
// Also zeroes the per-panel counters for the GEMM (fresh each graph replay).
// Block b -> (ot = b>>5, g = b&31):
//   mixP[c][dd] = mix_w[ot*64+c, sig(g*64+dd)],  sig(m) = (m%32)*64 + m/32
//   KEY: sig(g*64+dd) = 64*(dd&31) + 2g + (dd>>5), so columns come in the
//   adjacent pairs {64k+2g, 64k+2g+1} -> ONE float2 load yields mixP[c][k]
//   and mixP[c][k+32] (coalesced-pair gather, 2x sector efficiency, MLP 8).
//   M[oo][dd] = sum_c stage2[ot*64+c, oo] * mixP[c][dd]
//   W[ot*64+oo, g*64+c2] = sum_dd M[oo][dd] * stage1[g*64+c2, dd]
// ============================================================================
__global__ __launch_bounds__(256)
void fold_kernel(const float* __restrict__ stage1,
                 const float* __restrict__ stage2,
                 const float* __restrict__ mix_w) {
    __shared__ float bufA[64 * 65];
    __shared__ float bufB[64 * 65];

    const int b = blockIdx.x;
    const int tid = threadIdx.x;
    const int ot = b >> 5, g = b & 31;

    if (b == 0 && tid < TOK / 128) g_cnt[tid] = 0;   // reset panel counters

    // Phase A: stage2 block [c][d]  +  pair-gathered mix_w block [c][dd]
    for (int i = tid; i < 64 * 64; i += 256) {
        int c = i >> 6, d = i & 63;
        bufA[c * 64 + d] = stage2[(ot * 64 + c) * 64 + d];
    }
#pragma unroll
    for (int it = 0; it < 8; it++) {
        int i = tid + it * 256;                // 0..2047 -> (c, k)
        int c = i >> 5, k = i & 31;
        float2 v = *(const float2*)(mix_w +
                     (size_t)(ot * 64 + c) * F + 64 * k + 2 * g);
        bufB[c * 64 + k]      = v.x;           // mixP[c][k]      (dd = k)
        bufB[c * 64 + k + 32] = v.y;           // mixP[c][k+32]   (dd = k+32)
    }
    __syncthreads();

    // Phase B: M-block partial. thread owns column dd=j, rows q*16..+15
    const int j = tid & 63, q = tid >> 6;
    float macc[16];
#pragma unroll
    for (int k = 0; k < 16; k++) macc[k] = 0.0f;
    for (int c = 0; c < 64; c++) {
        float mx = bufB[c * 64 + j];
#pragma unroll
        for (int k = 0; k < 16; k++) macc[k] += bufA[c * 64 + q * 16 + k] * mx;
    }
    __syncthreads();

    // Phase C: materialize M (stride 65) into bufA; load stage1 into bufB
#pragma unroll
    for (int k = 0; k < 16; k++) bufA[(q * 16 + k) * 65 + j] = macc[k];
    for (int i = tid; i < 64 * 64; i += 256) {
        int c2 = i >> 6, dd = i & 63;
        bufB[c2 * 65 + dd] = stage1[(g * 64 + c2) * 64 + dd];
    }
    __syncthreads();

    // Phase D: contract with stage1
    const int c2 = tid & 63;
    float wacc[16];
#pragma unroll
    for (int k = 0; k < 16; k++) wacc[k] = 0.0f;
    for (int dd = 0; dd < 64; dd++) {
        float w1 = bufB[c2 * 65 + dd];
#pragma unroll
        for (int k = 0; k < 16; k++) wacc[k] += bufA[(q * 16 + k) * 65 + dd] * w1;
    }
#pragma unroll
    for (int k = 0; k < 16; k++)
        g_W[(size_t)(ot * 64 + q * 16 + k) * F + g * 64 + c2] = __float2half_rn(wacc[k]);
}

// ============================================================================
// Main GEMM: out[t, o] = sum_k x[t,k] * W[o,k]   (fp16 inputs, fp32 accum)
// Inline distributed x->fp16 conversion: the 16 CTAs sharing token-panel by
// each convert a disjoint 8-row slice, then rendezvous on a panel counter.
// CTA tile 128x128, K chunk 64, 3-stage cp.async pipeline, 8 warps (2x4).
// ============================================================================
static constexpr int BM = 128, BN = 128, BK = 64, STAGES = 3;
static constexpr int A_STAGE_BYTES = BM * BK * 2;               // 16384
static constexpr int STAGE_BYTES   = (BM + BN) * BK * 2;        // 32768
static constexpr int SMEM_BYTES    = STAGES * STAGE_BYTES;      // 98304

__global__ __launch_bounds__(256, 2)
void gemm_kernel(const float* __restrict__ x, float* __restrict__ out) {
    extern __shared__ char smem[];
    const uint32_t sbase = smem_to_u32(smem);
    const int tid  = threadIdx.x;
    const int lane = tid & 31, wid = tid >> 5;
    const int m0 = blockIdx.y * BM;
    const int n0 = blockIdx.x * BN;
    const int wm = (wid >> 2) * 64;     // warp m-origin in tile
    const int wn = (wid & 3) * 32;      // warp n-origin in tile

    // ---- distributed conversion: blockIdx.x owns 8 rows of panel m0 ----
    {
        const size_t base = ((size_t)m0 + (size_t)blockIdx.x * 8) * F;
#pragma unroll 8
        for (int it = 0; it < 16; it++) {
            size_t off = base + (size_t)it * 1024 + (size_t)tid * 4;
            float4 v = *(const float4*)(x + off);
            __half2 h0 = __floats2half2_rn(v.x, v.y);
            __half2 h1 = __floats2half2_rn(v.z, v.w);
            uint2 w;
            w.x = *(uint32_t*)&h0; w.y = *(uint32_t*)&h1;
            *(uint2*)(g_X + off) = w;
        }
        __threadfence();
        __syncthreads();
        if (tid == 0) {
            atomicAdd(&g_cnt[blockIdx.y], 1u);
            while (ld_acquire_gpu(&g_cnt[blockIdx.y]) < 16u) { }
        }
        __syncthreads();
    }

    // ---- cp.async geometry: 4 x 16B per thread per operand per stage ----
    uint32_t dst_off[4];
    size_t   srcA[4], srcB[4];
#pragma unroll
    for (int i = 0; i < 4; i++) {
        int u = tid + 256 * i;                // 0..1023
        int row = u >> 3, seg = u & 7;        // 128 rows x 8 segs of 16B
        dst_off[i] = (uint32_t)(row * 128 + ((seg ^ (row & 7)) * 16));
        srcA[i] = (size_t)(m0 + row) * F + seg * 8;
        srcB[i] = (size_t)(n0 + row) * F + seg * 8;
    }
    const __half* gA = g_X;
    const __half* gB = g_W;

    auto issue_stage = [&](int kc, int st) {
        uint32_t sA = sbase + st * STAGE_BYTES;
        uint32_t sB = sA + A_STAGE_BYTES;
        const __half* pa = gA + (size_t)kc * BK;
        const __half* pb = gB + (size_t)kc * BK;
#pragma unroll
        for (int i = 0; i < 4; i++) {
            asm volatile("cp.async.cg.shared.global [%0], [%1], 16;"
                         :: "r"(sA + dst_off[i]), "l"(pa + srcA[i]) : "memory");
            asm volatile("cp.async.cg.shared.global [%0], [%1], 16;"
                         :: "r"(sB + dst_off[i]), "l"(pb + srcB[i]) : "memory");
        }
    };

    // ---- ldmatrix per-lane addressing ----
    const uint32_t aRow = (uint32_t)(wm + (lane & 15));
    const uint32_t bRow = (uint32_t)(wn + ((lane & 7) | ((lane & 16) >> 1)));
    uint32_t xsA[4], xsB[4];
#pragma unroll
    for (int ks = 0; ks < 4; ks++) {
        xsA[ks] = (uint32_t)(((ks * 2 + (lane >> 4)) ^ (lane & 7)) * 16);
        xsB[ks] = (uint32_t)(((ks * 2 + ((lane >> 3) & 1)) ^ (lane & 7)) * 16);
    }
    const uint32_t aBase = aRow * 128u;
    const uint32_t bBase = bRow * 128u;

    float acc[4][4][4];
#pragma unroll
    for (int fm = 0; fm < 4; fm++)
#pragma unroll
        for (int fn = 0; fn < 4; fn++)
#pragma unroll
            for (int k = 0; k < 4; k++) acc[fm][fn][k] = 0.0f;

    auto compute_stage = [&](int st) {
        uint32_t sA = sbase + st * STAGE_BYTES + aBase;
        uint32_t sB = sbase + st * STAGE_BYTES + A_STAGE_BYTES + bBase;
#pragma unroll
        for (int ks = 0; ks < 4; ks++) {
            uint32_t a[4][4], b[8];
#pragma unroll
            for (int fm = 0; fm < 4; fm++) {
                uint32_t addr = sA + (uint32_t)(fm * 2048) + xsA[ks];
                asm volatile(
                    "ldmatrix.sync.aligned.m8n8.x4.shared.b16 {%0,%1,%2,%3}, [%4];"
                    : "=r"(a[fm][0]), "=r"(a[fm][1]), "=r"(a[fm][2]), "=r"(a[fm][3])
                    : "r"(addr));
            }
#pragma unroll
            for (int p = 0; p < 2; p++) {
                uint32_t addr = sB + (uint32_t)(p * 2048) + xsB[ks];
                asm volatile(
                    "ldmatrix.sync.aligned.m8n8.x4.shared.b16 {%0,%1,%2,%3}, [%4];"
                    : "=r"(b[p*4+0]), "=r"(b[p*4+1]), "=r"(b[p*4+2]), "=r"(b[p*4+3])
                    : "r"(addr));
            }
#pragma unroll
            for (int fm = 0; fm < 4; fm++) {
#pragma unroll
                for (int fn = 0; fn < 4; fn++) {
                    uint32_t b0 = b[(fn >> 1) * 4 + (fn & 1) * 2];
                    uint32_t b1 = b[(fn >> 1) * 4 + (fn & 1) * 2 + 1];
                    asm volatile(
                        "mma.sync.aligned.m16n8k16.row.col.f32.f16.f16.f32 "
                        "{%0,%1,%2,%3}, {%4,%5,%6,%7}, {%8,%9}, {%0,%1,%2,%3};"
                        : "+f"(acc[fm][fn][0]), "+f"(acc[fm][fn][1]),
                          "+f"(acc[fm][fn][2]), "+f"(acc[fm][fn][3])
                        : "r"(a[fm][0]), "r"(a[fm][1]), "r"(a[fm][2]), "r"(a[fm][3]),
                          "r"(b0), "r"(b1));
                }
            }
        }
    };

    // ---- pipeline ----
    issue_stage(0, 0);
    asm volatile("cp.async.commit_group;" ::: "memory");
    issue_stage(1, 1);
    asm volatile("cp.async.commit_group;" ::: "memory");

    const int NCHUNK = F / BK;   // 32
    for (int kc = 0; kc < NCHUNK; kc++) {
        asm volatile("cp.async.wait_group 1;" ::: "memory");
        __syncthreads();
        if (kc + 2 < NCHUNK) {
            int nxt = kc + 2;
            issue_stage(nxt, nxt % STAGES);
        }
        asm volatile("cp.async.commit_group;" ::: "memory");
        compute_stage(kc % STAGES);
    }

    // ---- epilogue: direct fp32 stores ----
#pragma unroll
    for (int fm = 0; fm < 4; fm++) {
#pragma unroll
        for (int fn = 0; fn < 4; fn++) {
            int r = m0 + wm + fm * 16 + (lane >> 2);
            int c = n0 + wn + fn * 8 + (lane & 3) * 2;
            float2 v0 = make_float2(acc[fm][fn][0], acc[fm][fn][1]);
            float2 v1 = make_float2(acc[fm][fn][2], acc[fm][fn][3]);
            *(float2*)(out + (size_t)r * F + c)       = v0;
            *(float2*)(out + (size_t)(r + 8) * F + c) = v1;
        }
    }
}

// ============================================================================
// Launch
// ============================================================================
extern "C" void kernel_launch(void* const* d_in, const int* in_sizes, int n_in,
                              void* d_out, int out_size) {
    const float* x      = (const float*)d_in[0];
    const float* stage1 = (const float*)d_in[1];
    const float* stage2 = (const float*)d_in[2];
    const float* mix_w  = (const float*)d_in[3];
    float* out = (float*)d_out;

    cudaFuncSetAttribute(gemm_kernel,
                         cudaFuncAttributeMaxDynamicSharedMemorySize, SMEM_BYTES);

    fold_kernel<<<1024, 256>>>(stage1, stage2, mix_w);
    gemm_kernel<<<dim3(F / BN, TOK / BM), 256, SMEM_BYTES>>>(x, out);
}